// round 6
// baseline (speedup 1.0000x reference)
#include <cuda_runtime.h>
#include <math.h>

#define Bn 4
#define Nn 2048
#define IND 128
#define Hn 4
#define Dn 64
#define C 256   // H*D
#define ROWS (Bn*Nn)   // 8192
#define LOG2E 1.4426950408889634f

// ---- scratch (static device globals; no allocation) ----
__device__ float g_Wh[ROWS*C];                    // [B*N, 256] fp32
__device__ unsigned int g_WhT[Bn*Hn*Dn*Nn];       // tf32 bits, [b][h][d][n]
__device__ unsigned int g_mask[Nn*64];            // adj bitmask: word n*64 + j/32
__device__ float g_src[Bn*Hn*Nn];                 // pre-scaled by LOG2E
__device__ float g_dst[Bn*Hn*Nn];                 // pre-scaled by LOG2E
__device__ float g_hnew[ROWS*C];
__device__ float g_psum[128*C];
__device__ float g_psq[128*C];
__device__ float g_mean[C];
__device__ float g_rstd[C];

__device__ __forceinline__ unsigned int f2tf32(float x) {
    unsigned int r;
    asm("cvt.rna.tf32.f32 %0, %1;" : "=r"(r) : "f"(x));
    return r;
}
__device__ __forceinline__ float ex2(float x) {
    float r;
    asm("ex2.approx.f32 %0, %1;" : "=f"(r) : "f"(x));
    return r;
}
__device__ __forceinline__ void mma_tf32(float* c,
                                         unsigned int a0, unsigned int a1,
                                         unsigned int a2, unsigned int a3,
                                         unsigned int b0, unsigned int b1) {
    asm("mma.sync.aligned.m16n8k8.row.col.f32.tf32.tf32.f32 "
        "{%0,%1,%2,%3}, {%4,%5,%6,%7}, {%8,%9}, {%0,%1,%2,%3};"
        : "+f"(c[0]), "+f"(c[1]), "+f"(c[2]), "+f"(c[3])
        : "r"(a0), "r"(a1), "r"(a2), "r"(a3), "r"(b0), "r"(b1));
}
__device__ __forceinline__ void cp16(unsigned int saddr, const void* gptr) {
    asm volatile("cp.async.cg.shared.global [%0], [%1], 16;" :: "r"(saddr), "l"(gptr));
}
__device__ __forceinline__ void cp4(unsigned int saddr, const void* gptr) {
    asm volatile("cp.async.ca.shared.global [%0], [%1], 4;" :: "r"(saddr), "l"(gptr));
}

// ============================================================
// K1: Wh = h @ W ; also emit transposed tf32 copy g_WhT[b][h][d][n]
// ============================================================
__global__ __launch_bounds__(256) void k_gemm(const float* __restrict__ hIn,
                                              const float* __restrict__ W) {
    __shared__ float hs[32 * IND];
    int row0 = blockIdx.x * 32;
    const float4* gp = (const float4*)(hIn + (size_t)row0 * IND);
    float4* sp = (float4*)hs;
    for (int i = threadIdx.x; i < 32 * IND / 4; i += 256) sp[i] = gp[i];
    __syncthreads();

    int c = threadIdx.x;
    float acc[32];
#pragma unroll
    for (int r = 0; r < 32; r++) acc[r] = 0.f;

    for (int k = 0; k < IND; k += 4) {
        float w0 = __ldg(&W[(k + 0) * C + c]);
        float w1 = __ldg(&W[(k + 1) * C + c]);
        float w2 = __ldg(&W[(k + 2) * C + c]);
        float w3 = __ldg(&W[(k + 3) * C + c]);
#pragma unroll
        for (int r = 0; r < 32; r++) {
            float4 hv = *(const float4*)&hs[r * IND + k];
            acc[r] += hv.x * w0 + hv.y * w1 + hv.z * w2 + hv.w * w3;
        }
    }
#pragma unroll
    for (int r = 0; r < 32; r++) g_Wh[(size_t)(row0 + r) * C + c] = acc[r];

    // transposed tf32 copy: rows row0..row0+31 stay inside one b (2048 % 32 == 0)
    int b = row0 >> 11;
    int n0 = row0 & (Nn - 1);
    int hh = c >> 6, d = c & 63;
    unsigned int* wt = g_WhT + (size_t)(((b * Hn + hh) * Dn + d)) * Nn + n0;
#pragma unroll
    for (int r8 = 0; r8 < 8; r8++) {
        uint4 v;
        v.x = f2tf32(acc[4 * r8 + 0]);
        v.y = f2tf32(acc[4 * r8 + 1]);
        v.z = f2tf32(acc[4 * r8 + 2]);
        v.w = f2tf32(acc[4 * r8 + 3]);
        ((uint4*)wt)[r8] = v;
    }
}

// ============================================================
// K2: src/dst projections (pre-scaled by LOG2E). One warp per (b,n,h).
// ============================================================
__global__ __launch_bounds__(256) void k_srcdst(const float* __restrict__ a) {
    int gw = blockIdx.x * 8 + (threadIdx.x >> 5);
    int lane = threadIdx.x & 31;
    int hh = gw & 3;
    int n  = (gw >> 2) & (Nn - 1);
    int b  = gw >> 13;
    const float2 v  = ((const float2*)(g_Wh + (size_t)(b * Nn + n) * C + hh * Dn))[lane];
    const float2 a1 = ((const float2*)(a + hh * 2 * Dn))[lane];
    const float2 a2 = ((const float2*)(a + hh * 2 * Dn + Dn))[lane];
    float s = v.x * a1.x + v.y * a1.y;
    float d = v.x * a2.x + v.y * a2.y;
#pragma unroll
    for (int o = 16; o > 0; o >>= 1) {
        s += __shfl_xor_sync(0xffffffffu, s, o);
        d += __shfl_xor_sync(0xffffffffu, d, o);
    }
    if (lane == 0) {
        g_src[(b * Hn + hh) * Nn + n] = s * LOG2E;
        g_dst[(b * Hn + hh) * Nn + n] = d * LOG2E;
    }
}

// ============================================================
// K2b: pack adjacency into bitmask. Warp covers 128 j of one row.
// ============================================================
__global__ __launch_bounds__(256) void k_pack(const int* __restrict__ adj) {
    int gw = blockIdx.x * 8 + (threadIdx.x >> 5);
    int lane = threadIdx.x & 31;
    int row = gw >> 4;
    int seg = gw & 15;             // 128-j segment
    const int* ap = adj + (size_t)row * Nn + seg * 128;
    unsigned int b0 = __ballot_sync(0xffffffffu, ap[lane] != 0);
    unsigned int b1 = __ballot_sync(0xffffffffu, ap[32 + lane] != 0);
    unsigned int b2 = __ballot_sync(0xffffffffu, ap[64 + lane] != 0);
    unsigned int b3 = __ballot_sync(0xffffffffu, ap[96 + lane] != 0);
    if (lane < 4) {
        unsigned int bb = (lane == 0) ? b0 : (lane == 1) ? b1 : (lane == 2) ? b2 : b3;
        g_mask[row * 64 + seg * 4 + lane] = bb;
    }
}

// ============================================================
// K3: attention. 256 blocks, 256 thr, tile 128 i x 64 d, 32 j-tiles.
// cp.async double-buffer, per-q interleaved P (8 regs), 3 CTAs/SM.
// ============================================================
__global__ __launch_bounds__(256, 3) void k_attn() {
    __shared__ unsigned int WhT_s[2][64 * 64];   // [d][j], chunk ^= 4*(d&3)
    __shared__ float dst_s[2][64];
    __shared__ unsigned int mask_s[2][256];

    int b  = blockIdx.z, hh = blockIdx.y;
    int i0 = blockIdx.x * 128;
    int t  = threadIdx.x;
    int w  = t >> 5, lane = t & 31;
    int gid = lane >> 2, tig = lane & 3;
    int g3 = gid & 3;

    int r0i = i0 + 16 * w + gid;
    const float* sb = g_src + (b * Hn + hh) * Nn;
    float src0 = sb[r0i];
    float src1 = sb[r0i + 8];

    float acc[8][4];
#pragma unroll
    for (int dt = 0; dt < 8; dt++)
#pragma unroll
        for (int r = 0; r < 4; r++) acc[dt][r] = 0.f;

    float rs0 = 0.f, rs1 = 0.f;

    const unsigned int* WhTg = g_WhT + (size_t)((b * Hn + hh) * Dn) * Nn;
    const float* db = g_dst + (b * Hn + hh) * Nn;
    const unsigned int* mb = g_mask + (size_t)i0 * 64;

    int d_l = t >> 2, c4 = t & 3;      // WhT coop-load mapping
    int mrow = t >> 1, mw = t & 1;     // mask coop load
    int ma = 16 * w + gid;             // phase-A mask rows

    // precompute smem byte addresses for staging (buffer 0; buffer 1 offsets added)
    unsigned int whbase0 = (unsigned int)__cvta_generic_to_shared(&WhT_s[0][d_l * 64]);
    unsigned int dstaddr0 = (unsigned int)__cvta_generic_to_shared(&dst_s[0][t & 63]);
    unsigned int mskaddr0 = (unsigned int)__cvta_generic_to_shared(&mask_s[0][t]);
    const unsigned int WHSTRIDE = 64 * 64 * 4;
    const unsigned int DSTSTRIDE = (unsigned int)((char*)&dst_s[1][0] - (char*)&dst_s[0][0]);
    const unsigned int MSKSTRIDE = (unsigned int)((char*)&mask_s[1][0] - (char*)&mask_s[0][0]);

    // ---- stage tile 0 into buffer 0 ----
    {
        const unsigned int* gsrc = WhTg + (size_t)d_l * Nn + 4 * c4;
#pragma unroll
        for (int u = 0; u < 4; u++)
            cp16(whbase0 + 16 * (c4 + 4 * (u ^ (d_l & 3))), gsrc + 16 * u);
        if (t < 64) cp4(dstaddr0, db + t);
        cp4(mskaddr0, mb + (size_t)mrow * 64 + mw);
        asm volatile("cp.async.commit_group;");
    }

    for (int jt = 0; jt < 32; jt++) {
        int cur = jt & 1;
        asm volatile("cp.async.wait_group 0;");
        __syncthreads();

        // stage next tile into other buffer (overlaps with compute below)
        if (jt + 1 < 32) {
            int nxt = cur ^ 1;
            int j0n = (jt + 1) * 64;
            const unsigned int* gsrc = WhTg + (size_t)d_l * Nn + j0n + 4 * c4;
            unsigned int whb = whbase0 + nxt * WHSTRIDE;
#pragma unroll
            for (int u = 0; u < 4; u++)
                cp16(whb + 16 * (c4 + 4 * (u ^ (d_l & 3))), gsrc + 16 * u);
            if (t < 64) cp4(dstaddr0 + nxt * DSTSTRIDE, db + j0n + t);
            cp4(mskaddr0 + nxt * MSKSTRIDE, mb + (size_t)mrow * 64 + (jt + 1) * 2 + mw);
            asm volatile("cp.async.commit_group;");
        }

        unsigned int mk0a = mask_s[cur][ma * 2];
        unsigned int mk0b = mask_s[cur][ma * 2 + 1];
        unsigned int mk1a = mask_s[cur][(ma + 8) * 2];
        unsigned int mk1b = mask_s[cur][(ma + 8) * 2 + 1];

#pragma unroll
        for (int q = 0; q < 4; q++) {
            // ---- phase A for this k-chunk: j = 16q + 4tig + u ----
            float4 dstv = *(const float4*)&dst_s[cur][16 * q + 4 * tig];
            unsigned int mw0 = (q < 2) ? mk0a : mk0b;
            unsigned int mw1 = (q < 2) ? mk1a : mk1b;
            int shb = 16 * (q & 1) + 4 * tig;
            float p0[4], p1[4];
#pragma unroll
            for (int u = 0; u < 4; u++) {
                float dj = (u == 0) ? dstv.x : (u == 1) ? dstv.y : (u == 2) ? dstv.z : dstv.w;
                float e0 = src0 + dj;
                float e1 = src1 + dj;
                e0 = fmaxf(e0, 0.2f * e0);
                e1 = fmaxf(e1, 0.2f * e1);
                p0[u] = ((mw0 >> (shb + u)) & 1u) ? ex2(e0) : 0.f;
                p1[u] = ((mw1 >> (shb + u)) & 1u) ? ex2(e1) : 0.f;
                rs0 += p0[u]; rs1 += p1[u];
            }
            // ---- phase B: 16 MMAs consuming these P ----
            int cq = q ^ g3;
            const uint4* bp = (const uint4*)&WhT_s[cur][0] + gid * 16 + 4 * cq + tig;
            unsigned int a00 = __float_as_uint(p0[0]);
            unsigned int a10 = __float_as_uint(p1[0]);
            unsigned int a20 = __float_as_uint(p0[1]);
            unsigned int a30 = __float_as_uint(p1[1]);
            unsigned int a01 = __float_as_uint(p0[2]);
            unsigned int a11 = __float_as_uint(p1[2]);
            unsigned int a21 = __float_as_uint(p0[3]);
            unsigned int a31 = __float_as_uint(p1[3]);
#pragma unroll
            for (int dt = 0; dt < 8; dt++) {
                uint4 v = bp[dt * 128];
                mma_tf32(acc[dt], a00, a10, a20, a30, v.x, v.y);
                mma_tf32(acc[dt], a01, a11, a21, a31, v.z, v.w);
            }
        }
    }

    // rowsum reduce over tig (lane bits 0..1)
    rs0 += __shfl_xor_sync(0xffffffffu, rs0, 1);
    rs0 += __shfl_xor_sync(0xffffffffu, rs0, 2);
    rs1 += __shfl_xor_sync(0xffffffffu, rs1, 1);
    rs1 += __shfl_xor_sync(0xffffffffu, rs1, 2);
    float inv0 = rs0 > 0.f ? 1.f / rs0 : 0.f;
    float inv1 = rs1 > 0.f ? 1.f / rs1 : 0.f;

    float* o0 = g_hnew + (size_t)(b * Nn + r0i) * C + hh * Dn;
    float* o1 = g_hnew + (size_t)(b * Nn + r0i + 8) * C + hh * Dn;
#pragma unroll
    for (int dt = 0; dt < 8; dt++) {
        int d = 8 * dt + 2 * tig;
        *(float2*)&o0[d] = make_float2(acc[dt][0] * inv0, acc[dt][1] * inv0);
        *(float2*)&o1[d] = make_float2(acc[dt][2] * inv1, acc[dt][3] * inv1);
    }
}

// ============================================================
// K4/K5: BatchNorm stats (deterministic two-stage)
// ============================================================
__global__ __launch_bounds__(256) void k_bn_partial() {
    int c = threadIdx.x;
    int r0 = blockIdx.x * 64;
    float s = 0.f, ss = 0.f;
    for (int r = 0; r < 64; r++) {
        float x = g_hnew[(size_t)(r0 + r) * C + c];
        s += x; ss += x * x;
    }
    g_psum[blockIdx.x * C + c] = s;
    g_psq [blockIdx.x * C + c] = ss;
}

__global__ __launch_bounds__(256) void k_bn_final() {
    int c = threadIdx.x;
    float s = 0.f, ss = 0.f;
    for (int k = 0; k < 128; k++) {
        s  += g_psum[k * C + c];
        ss += g_psq [k * C + c];
    }
    float m = s * (1.f / (float)ROWS);
    float v = ss * (1.f / (float)ROWS) - m * m;
    v = v > 0.f ? v : 0.f;
    g_mean[c] = m;
    g_rstd[c] = rsqrtf(v + 1e-5f);
}

// ============================================================
// K6: normalize + affine + ELU
// ============================================================
__global__ __launch_bounds__(256) void k_norm(const float* __restrict__ gamma,
                                              const float* __restrict__ beta,
                                              float* __restrict__ out) {
    int idx = blockIdx.x * 256 + threadIdx.x;   // float4 index
    int c = (idx & 63) * 4;                     // channel of .x
    float4 x = ((const float4*)g_hnew)[idx];
    float4 y;
    y.x = (x.x - g_mean[c + 0]) * g_rstd[c + 0] * gamma[c + 0] + beta[c + 0];
    y.y = (x.y - g_mean[c + 1]) * g_rstd[c + 1] * gamma[c + 1] + beta[c + 1];
    y.z = (x.z - g_mean[c + 2]) * g_rstd[c + 2] * gamma[c + 2] + beta[c + 2];
    y.w = (x.w - g_mean[c + 3]) * g_rstd[c + 3] * gamma[c + 3] + beta[c + 3];
    y.x = y.x > 0.f ? y.x : expm1f(y.x);
    y.y = y.y > 0.f ? y.y : expm1f(y.y);
    y.z = y.z > 0.f ? y.z : expm1f(y.z);
    y.w = y.w > 0.f ? y.w : expm1f(y.w);
    ((float4*)out)[idx] = y;
}

// ============================================================
extern "C" void kernel_launch(void* const* d_in, const int* in_sizes, int n_in,
                              void* d_out, int out_size) {
    const float* h     = (const float*)d_in[0];
    const float* W     = (const float*)d_in[1];
    const float* a     = (const float*)d_in[2];
    const float* gamma = (const float*)d_in[3];
    const float* beta  = (const float*)d_in[4];
    const int*   adj   = (const int*)d_in[5];
    float* out = (float*)d_out;

    k_gemm<<<ROWS / 32, 256>>>(h, W);
    k_srcdst<<<Bn * Nn * Hn / 8, 256>>>(a);
    k_pack<<<Nn * 16 / 8, 256>>>(adj);
    dim3 g(Nn / 128, Hn, Bn);      // 16 x 4 x 4 = 256 blocks, launch #4 for ncu
    k_attn<<<g, 256>>>();
    k_bn_partial<<<128, 256>>>();
    k_bn_final<<<1, 256>>>();
    k_norm<<<ROWS * C / 4 / 256, 256>>>(gamma, beta, out);
}

// round 8
// speedup vs baseline: 1.0898x; 1.0898x over previous
// R8 = R7 resubmit (R7 bench hit "GB300 container failed twice" = infra, kernel never ran)
#include <cuda_runtime.h>
#include <math.h>

#define Bn 4
#define Nn 2048
#define IND 128
#define Hn 4
#define Dn 64
#define C 256   // H*D
#define ROWS (Bn*Nn)   // 8192
#define LOG2E 1.4426950408889634f

// ---- scratch (static device globals; no allocation) ----
__device__ float g_Wh[ROWS*C];                    // [B*N, 256] fp32
__device__ unsigned int g_WhT[Bn*Hn*Dn*Nn];       // tf32 bits, [b][h][d][n]
__device__ unsigned int g_mask[Nn*64];            // adj bitmask: word n*64 + j/32
__device__ float g_src[Bn*Hn*Nn];                 // pre-scaled by LOG2E
__device__ float g_dst[Bn*Hn*Nn];                 // pre-scaled by LOG2E
__device__ float g_hnew[ROWS*C];
__device__ float g_psum[128*C];
__device__ float g_psq[128*C];
__device__ float g_mean[C];
__device__ float g_rstd[C];

__device__ __forceinline__ unsigned int f2tf32(float x) {
    unsigned int r;
    asm("cvt.rna.tf32.f32 %0, %1;" : "=r"(r) : "f"(x));
    return r;
}
__device__ __forceinline__ float ex2(float x) {
    float r;
    asm("ex2.approx.f32 %0, %1;" : "=f"(r) : "f"(x));
    return r;
}
__device__ __forceinline__ void mma_tf32(float* c,
                                         unsigned int a0, unsigned int a1,
                                         unsigned int a2, unsigned int a3,
                                         unsigned int b0, unsigned int b1) {
    asm("mma.sync.aligned.m16n8k8.row.col.f32.tf32.tf32.f32 "
        "{%0,%1,%2,%3}, {%4,%5,%6,%7}, {%8,%9}, {%0,%1,%2,%3};"
        : "+f"(c[0]), "+f"(c[1]), "+f"(c[2]), "+f"(c[3])
        : "r"(a0), "r"(a1), "r"(a2), "r"(a3), "r"(b0), "r"(b1));
}
__device__ __forceinline__ void cp16(unsigned int saddr, const void* gptr) {
    asm volatile("cp.async.cg.shared.global [%0], [%1], 16;" :: "r"(saddr), "l"(gptr));
}
__device__ __forceinline__ void cp8(unsigned int saddr, const void* gptr) {
    asm volatile("cp.async.ca.shared.global [%0], [%1], 8;" :: "r"(saddr), "l"(gptr));
}
__device__ __forceinline__ void cp4(unsigned int saddr, const void* gptr) {
    asm volatile("cp.async.ca.shared.global [%0], [%1], 4;" :: "r"(saddr), "l"(gptr));
}

// ============================================================
// K1: Wh = h @ W ; also emit transposed tf32 copy g_WhT[b][h][d][n]
// ============================================================
__global__ __launch_bounds__(256) void k_gemm(const float* __restrict__ hIn,
                                              const float* __restrict__ W) {
    __shared__ float hs[32 * IND];
    int row0 = blockIdx.x * 32;
    const float4* gp = (const float4*)(hIn + (size_t)row0 * IND);
    float4* sp = (float4*)hs;
    for (int i = threadIdx.x; i < 32 * IND / 4; i += 256) sp[i] = gp[i];
    __syncthreads();

    int c = threadIdx.x;
    float acc[32];
#pragma unroll
    for (int r = 0; r < 32; r++) acc[r] = 0.f;

    for (int k = 0; k < IND; k += 4) {
        float w0 = __ldg(&W[(k + 0) * C + c]);
        float w1 = __ldg(&W[(k + 1) * C + c]);
        float w2 = __ldg(&W[(k + 2) * C + c]);
        float w3 = __ldg(&W[(k + 3) * C + c]);
#pragma unroll
        for (int r = 0; r < 32; r++) {
            float4 hv = *(const float4*)&hs[r * IND + k];
            acc[r] += hv.x * w0 + hv.y * w1 + hv.z * w2 + hv.w * w3;
        }
    }
#pragma unroll
    for (int r = 0; r < 32; r++) g_Wh[(size_t)(row0 + r) * C + c] = acc[r];

    int b = row0 >> 11;
    int n0 = row0 & (Nn - 1);
    int hh = c >> 6, d = c & 63;
    unsigned int* wt = g_WhT + (size_t)(((b * Hn + hh) * Dn + d)) * Nn + n0;
#pragma unroll
    for (int r8 = 0; r8 < 8; r8++) {
        uint4 v;
        v.x = f2tf32(acc[4 * r8 + 0]);
        v.y = f2tf32(acc[4 * r8 + 1]);
        v.z = f2tf32(acc[4 * r8 + 2]);
        v.w = f2tf32(acc[4 * r8 + 3]);
        ((uint4*)wt)[r8] = v;
    }
}

// ============================================================
// K2: src/dst projections (pre-scaled by LOG2E). One warp per (b,n,h).
// ============================================================
__global__ __launch_bounds__(256) void k_srcdst(const float* __restrict__ a) {
    int gw = blockIdx.x * 8 + (threadIdx.x >> 5);
    int lane = threadIdx.x & 31;
    int hh = gw & 3;
    int n  = (gw >> 2) & (Nn - 1);
    int b  = gw >> 13;
    const float2 v  = ((const float2*)(g_Wh + (size_t)(b * Nn + n) * C + hh * Dn))[lane];
    const float2 a1 = ((const float2*)(a + hh * 2 * Dn))[lane];
    const float2 a2 = ((const float2*)(a + hh * 2 * Dn + Dn))[lane];
    float s = v.x * a1.x + v.y * a1.y;
    float d = v.x * a2.x + v.y * a2.y;
#pragma unroll
    for (int o = 16; o > 0; o >>= 1) {
        s += __shfl_xor_sync(0xffffffffu, s, o);
        d += __shfl_xor_sync(0xffffffffu, d, o);
    }
    if (lane == 0) {
        g_src[(b * Hn + hh) * Nn + n] = s * LOG2E;
        g_dst[(b * Hn + hh) * Nn + n] = d * LOG2E;
    }
}

// ============================================================
// K2b: pack adjacency into bitmask. Warp covers 128 j of one row.
// ============================================================
__global__ __launch_bounds__(256) void k_pack(const int* __restrict__ adj) {
    int gw = blockIdx.x * 8 + (threadIdx.x >> 5);
    int lane = threadIdx.x & 31;
    int row = gw >> 4;
    int seg = gw & 15;
    const int* ap = adj + (size_t)row * Nn + seg * 128;
    unsigned int b0 = __ballot_sync(0xffffffffu, ap[lane] != 0);
    unsigned int b1 = __ballot_sync(0xffffffffu, ap[32 + lane] != 0);
    unsigned int b2 = __ballot_sync(0xffffffffu, ap[64 + lane] != 0);
    unsigned int b3 = __ballot_sync(0xffffffffu, ap[96 + lane] != 0);
    if (lane < 4) {
        unsigned int bb = (lane == 0) ? b0 : (lane == 1) ? b1 : (lane == 2) ? b2 : b3;
        g_mask[row * 64 + seg * 4 + lane] = bb;
    }
}

// ============================================================
// K3: attention. 256 blocks x 128 thr. CTA tile 128 i x 64 d.
// 4 warps, each warp m32 (rows 32w..32w+31) -> every B LDS.128
// feeds 4 MMAs. Phase A fully batched (64 P regs) before phase B.
// cp.async double-buffer, one __syncthreads per j-tile.
// ============================================================
__global__ __launch_bounds__(128, 2) void k_attn() {
    __shared__ unsigned int WhT_s[2][64 * 64];   // [d][j], chunk ^= 4*(d&3)
    __shared__ float dst_s[2][64];
    __shared__ unsigned int mask_s[2][256];      // 128 rows x 2 words

    int b  = blockIdx.z, hh = blockIdx.y;
    int i0 = blockIdx.x * 128;
    int t  = threadIdx.x;
    int w  = t >> 5, lane = t & 31;
    int gid = lane >> 2, tig = lane & 3;
    int g3 = gid & 3;

    int ibase = 32 * w + gid;          // CTA-local row of rr=0
    const float* sb = g_src + (b * Hn + hh) * Nn + i0;
    float srcv[4];
#pragma unroll
    for (int rr = 0; rr < 4; rr++) srcv[rr] = sb[ibase + 8 * rr];

    float accA[8][4], accB[8][4];
#pragma unroll
    for (int dt = 0; dt < 8; dt++)
#pragma unroll
        for (int r = 0; r < 4; r++) { accA[dt][r] = 0.f; accB[dt][r] = 0.f; }

    float rs[4] = {0.f, 0.f, 0.f, 0.f};

    const unsigned int* WhTg = g_WhT + (size_t)((b * Hn + hh) * Dn) * Nn;
    const float* db = g_dst + (b * Hn + hh) * Nn;
    const unsigned int* mb = g_mask + (size_t)i0 * 64;

    int d_l = t >> 2, c4 = t & 3;      // staging: rows d_l and d_l+32, 4 chunks

    unsigned int whbase = (unsigned int)__cvta_generic_to_shared(&WhT_s[0][0]);
    unsigned int dstaddr0 = (unsigned int)__cvta_generic_to_shared(&dst_s[0][t & 63]);
    unsigned int mskaddr0 = (unsigned int)__cvta_generic_to_shared(&mask_s[0][2 * t]);
    const unsigned int WHSTRIDE = 64 * 64 * 4;
    const unsigned int DSTSTRIDE = (unsigned int)((char*)&dst_s[1][0] - (char*)&dst_s[0][0]);
    const unsigned int MSKSTRIDE = (unsigned int)((char*)&mask_s[1][0] - (char*)&mask_s[0][0]);

    // ---- stage tile 0 into buffer 0 ----
    {
        const unsigned int* g0 = WhTg + (size_t)d_l * Nn + 4 * c4;
        const unsigned int* g1 = WhTg + (size_t)(d_l + 32) * Nn + 4 * c4;
        unsigned int s0 = whbase + d_l * 256;
        unsigned int s1 = whbase + (d_l + 32) * 256;
        int sw = d_l & 3;   // same for d_l+32
#pragma unroll
        for (int u = 0; u < 4; u++) {
            cp16(s0 + 16 * (c4 + 4 * (u ^ sw)), g0 + 16 * u);
            cp16(s1 + 16 * (c4 + 4 * (u ^ sw)), g1 + 16 * u);
        }
        if (t < 64) cp4(dstaddr0, db + t);
        cp8(mskaddr0, mb + (size_t)t * 64);
        asm volatile("cp.async.commit_group;");
    }

    for (int jt = 0; jt < 32; jt++) {
        int cur = jt & 1;
        asm volatile("cp.async.wait_group 0;");
        __syncthreads();

        // stage next tile (overlaps with compute below)
        if (jt + 1 < 32) {
            int nxt = cur ^ 1;
            int j0n = (jt + 1) * 64;
            const unsigned int* g0 = WhTg + (size_t)d_l * Nn + j0n + 4 * c4;
            const unsigned int* g1 = WhTg + (size_t)(d_l + 32) * Nn + j0n + 4 * c4;
            unsigned int s0 = whbase + nxt * WHSTRIDE + d_l * 256;
            unsigned int s1 = whbase + nxt * WHSTRIDE + (d_l + 32) * 256;
            int sw = d_l & 3;
#pragma unroll
            for (int u = 0; u < 4; u++) {
                cp16(s0 + 16 * (c4 + 4 * (u ^ sw)), g0 + 16 * u);
                cp16(s1 + 16 * (c4 + 4 * (u ^ sw)), g1 + 16 * u);
            }
            if (t < 64) cp4(dstaddr0 + nxt * DSTSTRIDE, db + j0n + t);
            cp8(mskaddr0 + nxt * MSKSTRIDE, mb + (size_t)t * 64 + (jt + 1) * 2);
            asm volatile("cp.async.commit_group;");
        }

        // ---- phase A: ALL P for this j-tile (64 regs) ----
        unsigned int mk[4][2];
#pragma unroll
        for (int rr = 0; rr < 4; rr++) {
            int ir = ibase + 8 * rr;
            mk[rr][0] = mask_s[cur][2 * ir];
            mk[rr][1] = mask_s[cur][2 * ir + 1];
        }
        float P[4][4][4];   // [rr][m][u], j = 16m + 4tig + u
#pragma unroll
        for (int m = 0; m < 4; m++) {
            float4 dstv = *(const float4*)&dst_s[cur][16 * m + 4 * tig];
            int shb = 16 * (m & 1) + 4 * tig;
            int half = m >> 1;
#pragma unroll
            for (int rr = 0; rr < 4; rr++) {
                unsigned int mwv = mk[rr][half];
                float sv = srcv[rr];
#pragma unroll
                for (int u = 0; u < 4; u++) {
                    float dj = (u == 0) ? dstv.x : (u == 1) ? dstv.y : (u == 2) ? dstv.z : dstv.w;
                    float e = sv + dj;
                    e = fmaxf(e, 0.2f * e);
                    float p = ((mwv >> (shb + u)) & 1u) ? ex2(e) : 0.f;
                    rs[rr] += p;
                    P[rr][m][u] = p;
                }
            }
        }

        // ---- phase B: tensor-core PV; each B LDS.128 feeds 4 MMAs ----
#pragma unroll
        for (int q = 0; q < 4; q++) {
            int cq = q ^ g3;
            const uint4* bp = (const uint4*)&WhT_s[cur][0] + gid * 16 + 4 * cq + tig;
            unsigned int a00 = __float_as_uint(P[0][q][0]);
            unsigned int a10 = __float_as_uint(P[1][q][0]);
            unsigned int a20 = __float_as_uint(P[0][q][1]);
            unsigned int a30 = __float_as_uint(P[1][q][1]);
            unsigned int a01 = __float_as_uint(P[0][q][2]);
            unsigned int a11 = __float_as_uint(P[1][q][2]);
            unsigned int a21 = __float_as_uint(P[0][q][3]);
            unsigned int a31 = __float_as_uint(P[1][q][3]);
            unsigned int b00 = __float_as_uint(P[2][q][0]);
            unsigned int b10 = __float_as_uint(P[3][q][0]);
            unsigned int b20 = __float_as_uint(P[2][q][1]);
            unsigned int b30 = __float_as_uint(P[3][q][1]);
            unsigned int b01 = __float_as_uint(P[2][q][2]);
            unsigned int b11 = __float_as_uint(P[3][q][2]);
            unsigned int b21 = __float_as_uint(P[2][q][3]);
            unsigned int b31 = __float_as_uint(P[3][q][3]);
#pragma unroll
            for (int dt = 0; dt < 8; dt++) {
                uint4 v = bp[dt * 128];
                mma_tf32(accA[dt], a00, a10, a20, a30, v.x, v.y);
                mma_tf32(accA[dt], a01, a11, a21, a31, v.z, v.w);
                mma_tf32(accB[dt], b00, b10, b20, b30, v.x, v.y);
                mma_tf32(accB[dt], b01, b11, b21, b31, v.z, v.w);
            }
        }
    }

    // rowsum reduce over tig (lane bits 0..1)
#pragma unroll
    for (int rr = 0; rr < 4; rr++) {
        rs[rr] += __shfl_xor_sync(0xffffffffu, rs[rr], 1);
        rs[rr] += __shfl_xor_sync(0xffffffffu, rs[rr], 2);
    }
    float inv[4];
#pragma unroll
    for (int rr = 0; rr < 4; rr++) inv[rr] = rs[rr] > 0.f ? 1.f / rs[rr] : 0.f;

#pragma unroll
    for (int rr = 0; rr < 4; rr++) {
        float* o = g_hnew + (size_t)(b * Nn + i0 + ibase + 8 * rr) * C + hh * Dn;
        float (*ac)[4] = (rr < 2) ? accA : accB;
        int sel = 2 * (rr & 1);
#pragma unroll
        for (int dt = 0; dt < 8; dt++) {
            int d = 8 * dt + 2 * tig;
            *(float2*)&o[d] = make_float2(ac[dt][sel] * inv[rr], ac[dt][sel + 1] * inv[rr]);
        }
    }
}

// ============================================================
// K4/K5: BatchNorm stats (deterministic two-stage)
// ============================================================
__global__ __launch_bounds__(256) void k_bn_partial() {
    int c = threadIdx.x;
    int r0 = blockIdx.x * 64;
    float s = 0.f, ss = 0.f;
    for (int r = 0; r < 64; r++) {
        float x = g_hnew[(size_t)(r0 + r) * C + c];
        s += x; ss += x * x;
    }
    g_psum[blockIdx.x * C + c] = s;
    g_psq [blockIdx.x * C + c] = ss;
}

__global__ __launch_bounds__(256) void k_bn_final() {
    int c = threadIdx.x;
    float s = 0.f, ss = 0.f;
    for (int k = 0; k < 128; k++) {
        s  += g_psum[k * C + c];
        ss += g_psq [k * C + c];
    }
    float m = s * (1.f / (float)ROWS);
    float v = ss * (1.f / (float)ROWS) - m * m;
    v = v > 0.f ? v : 0.f;
    g_mean[c] = m;
    g_rstd[c] = rsqrtf(v + 1e-5f);
}

// ============================================================
// K6: normalize + affine + ELU
// ============================================================
__global__ __launch_bounds__(256) void k_norm(const float* __restrict__ gamma,
                                              const float* __restrict__ beta,
                                              float* __restrict__ out) {
    int idx = blockIdx.x * 256 + threadIdx.x;
    int c = (idx & 63) * 4;
    float4 x = ((const float4*)g_hnew)[idx];
    float4 y;
    y.x = (x.x - g_mean[c + 0]) * g_rstd[c + 0] * gamma[c + 0] + beta[c + 0];
    y.y = (x.y - g_mean[c + 1]) * g_rstd[c + 1] * gamma[c + 1] + beta[c + 1];
    y.z = (x.z - g_mean[c + 2]) * g_rstd[c + 2] * gamma[c + 2] + beta[c + 2];
    y.w = (x.w - g_mean[c + 3]) * g_rstd[c + 3] * gamma[c + 3] + beta[c + 3];
    y.x = y.x > 0.f ? y.x : expm1f(y.x);
    y.y = y.y > 0.f ? y.y : expm1f(y.y);
    y.z = y.z > 0.f ? y.z : expm1f(y.z);
    y.w = y.w > 0.f ? y.w : expm1f(y.w);
    ((float4*)out)[idx] = y;
}

// ============================================================
extern "C" void kernel_launch(void* const* d_in, const int* in_sizes, int n_in,
                              void* d_out, int out_size) {
    const float* h     = (const float*)d_in[0];
    const float* W     = (const float*)d_in[1];
    const float* a     = (const float*)d_in[2];
    const float* gamma = (const float*)d_in[3];
    const float* beta  = (const float*)d_in[4];
    const int*   adj   = (const int*)d_in[5];
    float* out = (float*)d_out;

    k_gemm<<<ROWS / 32, 256>>>(h, W);
    k_srcdst<<<Bn * Nn * Hn / 8, 256>>>(a);
    k_pack<<<Nn * 16 / 8, 256>>>(adj);
    dim3 g(Nn / 128, Hn, Bn);      // 16 x 4 x 4 = 256 blocks, launch #4 for ncu
    k_attn<<<g, 128>>>();
    k_bn_partial<<<128, 256>>>();
    k_bn_final<<<1, 256>>>();
    k_norm<<<ROWS * C / 4 / 256, 256>>>(gamma, beta, out);
}

// round 9
// speedup vs baseline: 1.1836x; 1.0861x over previous
#include <cuda_runtime.h>
#include <cuda_fp16.h>
#include <math.h>

#define Bn 4
#define Nn 2048
#define IND 128
#define Hn 4
#define Dn 64
#define C 256   // H*D
#define ROWS (Bn*Nn)   // 8192
#define LOG2E 1.4426950408889634f

// ---- scratch (static device globals; no allocation) ----
__device__ float g_Wh[ROWS*C];                    // [B*N, 256] fp32
__device__ unsigned int g_WhT[Bn*Hn*Dn*Nn/2];     // fp16 pairs, [b][h][d][n]
__device__ unsigned int g_mask[Nn*64];            // adj bitmask: word n*64 + j/32
__device__ float g_src[Bn*Hn*Nn];                 // pre-scaled by LOG2E
__device__ float g_dst[Bn*Hn*Nn];                 // pre-scaled by LOG2E
__device__ float g_hnew[ROWS*C];
__device__ float g_psum[256*C];
__device__ float g_psq[256*C];
__device__ float g_mean[C];
__device__ float g_rstd[C];

__device__ __forceinline__ float ex2(float x) {
    float r;
    asm("ex2.approx.f32 %0, %1;" : "=f"(r) : "f"(x));
    return r;
}
__device__ __forceinline__ unsigned int packh2(float a, float b) {
    __half2 h = __floats2half2_rn(a, b);   // low = a, high = b
    return *(unsigned int*)&h;
}
__device__ __forceinline__ void mma_f16(float* c,
                                        unsigned int a0, unsigned int a1,
                                        unsigned int a2, unsigned int a3,
                                        unsigned int b0, unsigned int b1) {
    asm("mma.sync.aligned.m16n8k16.row.col.f32.f16.f16.f32 "
        "{%0,%1,%2,%3}, {%4,%5,%6,%7}, {%8,%9}, {%0,%1,%2,%3};"
        : "+f"(c[0]), "+f"(c[1]), "+f"(c[2]), "+f"(c[3])
        : "r"(a0), "r"(a1), "r"(a2), "r"(a3), "r"(b0), "r"(b1));
}
__device__ __forceinline__ void cp16(unsigned int saddr, const void* gptr) {
    asm volatile("cp.async.cg.shared.global [%0], [%1], 16;" :: "r"(saddr), "l"(gptr));
}
__device__ __forceinline__ void cp8(unsigned int saddr, const void* gptr) {
    asm volatile("cp.async.ca.shared.global [%0], [%1], 8;" :: "r"(saddr), "l"(gptr));
}
__device__ __forceinline__ void cp4(unsigned int saddr, const void* gptr) {
    asm volatile("cp.async.ca.shared.global [%0], [%1], 4;" :: "r"(saddr), "l"(gptr));
}
__device__ __forceinline__ int sigma3(int g) {   // chunk-swizzle: {0,4,1,5,2,6,3,7}
    return ((g & 1) << 2) | (g >> 1);
}

// ============================================================
// K1: Wh = h @ W ; also emit transposed fp16 copy g_WhT[b][h][d][n]
// ============================================================
__global__ __launch_bounds__(256) void k_gemm(const float* __restrict__ hIn,
                                              const float* __restrict__ W) {
    __shared__ float hs[32 * IND];
    int row0 = blockIdx.x * 32;
    const float4* gp = (const float4*)(hIn + (size_t)row0 * IND);
    float4* sp = (float4*)hs;
    for (int i = threadIdx.x; i < 32 * IND / 4; i += 256) sp[i] = gp[i];
    __syncthreads();

    int c = threadIdx.x;
    float acc[32];
#pragma unroll
    for (int r = 0; r < 32; r++) acc[r] = 0.f;

    for (int k = 0; k < IND; k += 4) {
        float w0 = __ldg(&W[(k + 0) * C + c]);
        float w1 = __ldg(&W[(k + 1) * C + c]);
        float w2 = __ldg(&W[(k + 2) * C + c]);
        float w3 = __ldg(&W[(k + 3) * C + c]);
#pragma unroll
        for (int r = 0; r < 32; r++) {
            float4 hv = *(const float4*)&hs[r * IND + k];
            acc[r] += hv.x * w0 + hv.y * w1 + hv.z * w2 + hv.w * w3;
        }
    }
#pragma unroll
    for (int r = 0; r < 32; r++) g_Wh[(size_t)(row0 + r) * C + c] = acc[r];

    // transposed fp16 copy (rows stay inside one b: 2048 % 32 == 0)
    int b = row0 >> 11;
    int n0 = row0 & (Nn - 1);
    int hh = c >> 6, d = c & 63;
    unsigned int* wt = g_WhT + ((size_t)(((b * Hn + hh) * Dn + d)) * Nn + n0) / 2;
    unsigned int wbuf[16];
#pragma unroll
    for (int m = 0; m < 16; m++) wbuf[m] = packh2(acc[2 * m], acc[2 * m + 1]);
#pragma unroll
    for (int q = 0; q < 4; q++) ((uint4*)wt)[q] = ((uint4*)wbuf)[q];
}

// ============================================================
// K2: src/dst projections (pre-scaled by LOG2E). One warp per (b,n,h).
// ============================================================
__global__ __launch_bounds__(256) void k_srcdst(const float* __restrict__ a) {
    int gw = blockIdx.x * 8 + (threadIdx.x >> 5);
    int lane = threadIdx.x & 31;
    int hh = gw & 3;
    int n  = (gw >> 2) & (Nn - 1);
    int b  = gw >> 13;
    const float2 v  = ((const float2*)(g_Wh + (size_t)(b * Nn + n) * C + hh * Dn))[lane];
    const float2 a1 = ((const float2*)(a + hh * 2 * Dn))[lane];
    const float2 a2 = ((const float2*)(a + hh * 2 * Dn + Dn))[lane];
    float s = v.x * a1.x + v.y * a1.y;
    float d = v.x * a2.x + v.y * a2.y;
#pragma unroll
    for (int o = 16; o > 0; o >>= 1) {
        s += __shfl_xor_sync(0xffffffffu, s, o);
        d += __shfl_xor_sync(0xffffffffu, d, o);
    }
    if (lane == 0) {
        g_src[(b * Hn + hh) * Nn + n] = s * LOG2E;
        g_dst[(b * Hn + hh) * Nn + n] = d * LOG2E;
    }
}

// ============================================================
// K2b: pack adjacency into bitmask. Warp covers 128 j of one row.
// ============================================================
__global__ __launch_bounds__(256) void k_pack(const int* __restrict__ adj) {
    int gw = blockIdx.x * 8 + (threadIdx.x >> 5);
    int lane = threadIdx.x & 31;
    int row = gw >> 4;
    int seg = gw & 15;
    const int* ap = adj + (size_t)row * Nn + seg * 128;
    unsigned int b0 = __ballot_sync(0xffffffffu, ap[lane] != 0);
    unsigned int b1 = __ballot_sync(0xffffffffu, ap[32 + lane] != 0);
    unsigned int b2 = __ballot_sync(0xffffffffu, ap[64 + lane] != 0);
    unsigned int b3 = __ballot_sync(0xffffffffu, ap[96 + lane] != 0);
    if (lane < 4) {
        unsigned int bb = (lane == 0) ? b0 : (lane == 1) ? b1 : (lane == 2) ? b2 : b3;
        g_mask[row * 64 + seg * 4 + lane] = bb;
    }
}

// ============================================================
// K3: attention. 256 blocks x 128 thr. CTA tile 128 i x 64 d.
// 4 warps, each m32 x 64d. fp16 mma.m16n8k16.
// k-slot permutation: MMA ks, A-slots (2tig,2tig+1) <-> j (8tig+2ks, +1);
//                     slots (2tig+8,2tig+9) <-> j (32+8tig+2ks, +1).
// WhT fp16 tile [d][j], 8 chunks of 16B per row, phys = chunk ^ sigma3(d&7);
// B fragments: 2 LDS.128 per dt serve all 4 k-steps.
// cp.async double-buffer, one __syncthreads per j-tile.
// ============================================================
__global__ __launch_bounds__(128, 2) void k_attn() {
    __shared__ unsigned int WhT_s[2][64 * 32];   // fp16 pairs: [d][j/2]
    __shared__ float dst_s[2][64];
    __shared__ unsigned int mask_s[2][256];      // 128 rows x 2 words

    int b  = blockIdx.z, hh = blockIdx.y;
    int i0 = blockIdx.x * 128;
    int t  = threadIdx.x;
    int w  = t >> 5, lane = t & 31;
    int gid = lane >> 2, tig = lane & 3;
    int sg = sigma3(gid);

    int ibase = 32 * w + gid;
    const float* sb = g_src + (b * Hn + hh) * Nn + i0;
    float srcv[4];
#pragma unroll
    for (int rr = 0; rr < 4; rr++) srcv[rr] = sb[ibase + 8 * rr];

    float accA[8][4], accB[8][4];
#pragma unroll
    for (int dt = 0; dt < 8; dt++)
#pragma unroll
        for (int r = 0; r < 4; r++) { accA[dt][r] = 0.f; accB[dt][r] = 0.f; }

    float rs[4] = {0.f, 0.f, 0.f, 0.f};

    const unsigned int* WhTg = g_WhT + (size_t)((b * Hn + hh) * Dn) * (Nn / 2);
    const float* db = g_dst + (b * Hn + hh) * Nn;
    const unsigned int* mb = g_mask + (size_t)i0 * 64;

    // staging mapping: thread handles row d_l = t>>1, chunk-quad c2 = t&1
    int d_l = t >> 1, c2 = t & 1;
    int sgs = sigma3(d_l & 7);

    unsigned int whbase = (unsigned int)__cvta_generic_to_shared(&WhT_s[0][0]);
    unsigned int dstaddr0 = (unsigned int)__cvta_generic_to_shared(&dst_s[0][t & 63]);
    unsigned int mskaddr0 = (unsigned int)__cvta_generic_to_shared(&mask_s[0][2 * t]);
    const unsigned int WHSTRIDE = 64 * 32 * 4;   // 8192 B
    const unsigned int DSTSTRIDE = (unsigned int)((char*)&dst_s[1][0] - (char*)&dst_s[0][0]);
    const unsigned int MSKSTRIDE = (unsigned int)((char*)&mask_s[1][0] - (char*)&mask_s[0][0]);

    // ---- stage tile 0 into buffer 0 ----
    {
        const unsigned int* gsrc = WhTg + (size_t)d_l * (Nn / 2);
        unsigned int srow = whbase + d_l * 128;
#pragma unroll
        for (int u = 0; u < 4; u++) {
            int ch = 4 * c2 + u;
            cp16(srow + 16 * (ch ^ sgs), gsrc + 4 * ch);
        }
        if (t < 64) cp4(dstaddr0, db + t);
        cp8(mskaddr0, mb + (size_t)t * 64);
        asm volatile("cp.async.commit_group;");
    }

    for (int jt = 0; jt < 32; jt++) {
        int cur = jt & 1;
        asm volatile("cp.async.wait_group 0;");
        __syncthreads();

        // stage next tile (overlaps with compute below)
        if (jt + 1 < 32) {
            int nxt = cur ^ 1;
            int j0n = (jt + 1) * 64;
            const unsigned int* gsrc = WhTg + (size_t)d_l * (Nn / 2) + j0n / 2;
            unsigned int srow = whbase + nxt * WHSTRIDE + d_l * 128;
#pragma unroll
            for (int u = 0; u < 4; u++) {
                int ch = 4 * c2 + u;
                cp16(srow + 16 * (ch ^ sgs), gsrc + 4 * ch);
            }
            if (t < 64) cp4(dstaddr0 + nxt * DSTSTRIDE, db + j0n + t);
            cp8(mskaddr0 + nxt * MSKSTRIDE, mb + (size_t)t * 64 + (jt + 1) * 2);
            asm volatile("cp.async.commit_group;");
        }

        // ---- phase A: all P for this j-tile, packed to half2 ----
        unsigned int mk[4][2];
#pragma unroll
        for (int rr = 0; rr < 4; rr++) {
            int ir = ibase + 8 * rr;
            mk[rr][0] = mask_s[cur][2 * ir];
            mk[rr][1] = mask_s[cur][2 * ir + 1];
        }
        unsigned int pa[4][4][2];   // [rr][ks][v]
#pragma unroll
        for (int v = 0; v < 2; v++) {
            int jb = 32 * v + 8 * tig;
            float4 dv0 = *(const float4*)&dst_s[cur][jb];
            float4 dv1 = *(const float4*)&dst_s[cur][jb + 4];
            float dj[8] = {dv0.x, dv0.y, dv0.z, dv0.w, dv1.x, dv1.y, dv1.z, dv1.w};
#pragma unroll
            for (int rr = 0; rr < 4; rr++) {
                unsigned int mwv = mk[rr][v] >> (8 * tig);
                float sv = srcv[rr];
                float p[8];
#pragma unroll
                for (int c = 0; c < 8; c++) {
                    float e = sv + dj[c];
                    e = fmaxf(e, 0.2f * e);
                    p[c] = ((mwv >> c) & 1u) ? ex2(e) : 0.f;
                    rs[rr] += p[c];
                }
#pragma unroll
                for (int ks = 0; ks < 4; ks++)
                    pa[rr][ks][v] = packh2(p[2 * ks], p[2 * ks + 1]);
            }
        }

        // ---- phase B: fp16 tensor-core PV ----
        const uint4* tile4 = (const uint4*)&WhT_s[cur][0];
        int c0 = tig ^ sg;
#pragma unroll
        for (int dt = 0; dt < 8; dt++) {
            int rowq = (8 * dt + gid) * 8;
            uint4 v0 = tile4[rowq + c0];
            uint4 v1 = tile4[rowq + (c0 ^ 4)];
            unsigned int bw0[4], bw1[4];
            *(uint4*)bw0 = v0;
            *(uint4*)bw1 = v1;
#pragma unroll
            for (int ks = 0; ks < 4; ks++) {
                mma_f16(accA[dt], pa[0][ks][0], pa[1][ks][0], pa[0][ks][1], pa[1][ks][1],
                        bw0[ks], bw1[ks]);
                mma_f16(accB[dt], pa[2][ks][0], pa[3][ks][0], pa[2][ks][1], pa[3][ks][1],
                        bw0[ks], bw1[ks]);
            }
        }
    }

    // rowsum reduce over tig (lane bits 0..1)
#pragma unroll
    for (int rr = 0; rr < 4; rr++) {
        rs[rr] += __shfl_xor_sync(0xffffffffu, rs[rr], 1);
        rs[rr] += __shfl_xor_sync(0xffffffffu, rs[rr], 2);
    }
    float inv[4];
#pragma unroll
    for (int rr = 0; rr < 4; rr++) inv[rr] = rs[rr] > 0.f ? 1.f / rs[rr] : 0.f;

#pragma unroll
    for (int rr = 0; rr < 4; rr++) {
        float* o = g_hnew + (size_t)(b * Nn + i0 + ibase + 8 * rr) * C + hh * Dn;
        float (*ac)[4] = (rr < 2) ? accA : accB;
        int sel = 2 * (rr & 1);
#pragma unroll
        for (int dt = 0; dt < 8; dt++) {
            int d = 8 * dt + 2 * tig;
            *(float2*)&o[d] = make_float2(ac[dt][sel] * inv[rr], ac[dt][sel + 1] * inv[rr]);
        }
    }
}

// ============================================================
// K4/K5: BatchNorm stats (deterministic two-stage)
// ============================================================
__global__ __launch_bounds__(256) void k_bn_partial() {
    int c = threadIdx.x;
    int r0 = blockIdx.x * 32;
    float s = 0.f, ss = 0.f;
#pragma unroll 8
    for (int r = 0; r < 32; r++) {
        float x = g_hnew[(size_t)(r0 + r) * C + c];
        s += x; ss += x * x;
    }
    g_psum[blockIdx.x * C + c] = s;
    g_psq [blockIdx.x * C + c] = ss;
}

__global__ __launch_bounds__(256) void k_bn_final() {
    int c = threadIdx.x;
    float s = 0.f, ss = 0.f;
#pragma unroll 8
    for (int k = 0; k < 256; k++) {
        s  += g_psum[k * C + c];
        ss += g_psq [k * C + c];
    }
    float m = s * (1.f / (float)ROWS);
    float v = ss * (1.f / (float)ROWS) - m * m;
    v = v > 0.f ? v : 0.f;
    g_mean[c] = m;
    g_rstd[c] = rsqrtf(v + 1e-5f);
}

// ============================================================
// K6: normalize + affine + ELU
// ============================================================
__global__ __launch_bounds__(256) void k_norm(const float* __restrict__ gamma,
                                              const float* __restrict__ beta,
                                              float* __restrict__ out) {
    int idx = blockIdx.x * 256 + threadIdx.x;
    int c = (idx & 63) * 4;
    float4 x = ((const float4*)g_hnew)[idx];
    float4 y;
    y.x = (x.x - g_mean[c + 0]) * g_rstd[c + 0] * gamma[c + 0] + beta[c + 0];
    y.y = (x.y - g_mean[c + 1]) * g_rstd[c + 1] * gamma[c + 1] + beta[c + 1];
    y.z = (x.z - g_mean[c + 2]) * g_rstd[c + 2] * gamma[c + 2] + beta[c + 2];
    y.w = (x.w - g_mean[c + 3]) * g_rstd[c + 3] * gamma[c + 3] + beta[c + 3];
    y.x = y.x > 0.f ? y.x : expm1f(y.x);
    y.y = y.y > 0.f ? y.y : expm1f(y.y);
    y.z = y.z > 0.f ? y.z : expm1f(y.z);
    y.w = y.w > 0.f ? y.w : expm1f(y.w);
    ((float4*)out)[idx] = y;
}

// ============================================================
extern "C" void kernel_launch(void* const* d_in, const int* in_sizes, int n_in,
                              void* d_out, int out_size) {
    const float* h     = (const float*)d_in[0];
    const float* W     = (const float*)d_in[1];
    const float* a     = (const float*)d_in[2];
    const float* gamma = (const float*)d_in[3];
    const float* beta  = (const float*)d_in[4];
    const int*   adj   = (const int*)d_in[5];
    float* out = (float*)d_out;

    k_gemm<<<ROWS / 32, 256>>>(h, W);
    k_srcdst<<<Bn * Nn * Hn / 8, 256>>>(a);
    k_pack<<<Nn * 16 / 8, 256>>>(adj);
    dim3 g(Nn / 128, Hn, Bn);      // 16 x 4 x 4 = 256 blocks, launch #4 for ncu
    k_attn<<<g, 128>>>();
    k_bn_partial<<<256, 256>>>();
    k_bn_final<<<1, 256>>>();
    k_norm<<<ROWS * C / 4 / 256, 256>>>(gamma, beta, out);
}

// round 12
// speedup vs baseline: 1.2586x; 1.0633x over previous
#include <cuda_runtime.h>
#include <cuda_fp16.h>
#include <math.h>

#define Bn 4
#define Nn 2048
#define IND 128
#define Hn 4
#define Dn 64
#define C 256   // H*D
#define ROWS (Bn*Nn)   // 8192
#define LOG2E 1.4426950408889634f

// ---- scratch (static device globals; no allocation) ----
__device__ float g_Wh[ROWS*C];                    // [B*N, 256] fp32
__device__ unsigned int g_WhT[Bn*Hn*Dn*Nn/2];     // fp16 pairs, [b][h][d][n]
__device__ unsigned char g_maskb[(size_t)Nn*Nn];  // 0xFF / 0x00 per (i,j)
__device__ float g_src[Bn*Hn*Nn];                 // pre-scaled by LOG2E
__device__ float g_dst[Bn*Hn*Nn];                 // pre-scaled by LOG2E
__device__ float g_hnew[ROWS*C];
__device__ float g_psum[256*C];
__device__ float g_psq[256*C];
__device__ float g_mean[C];
__device__ float g_rstd[C];

__device__ __forceinline__ float ex2(float x) {
    float r;
    asm("ex2.approx.f32 %0, %1;" : "=f"(r) : "f"(x));
    return r;
}
__device__ __forceinline__ unsigned int packh2(float a, float b) {
    __half2 h = __floats2half2_rn(a, b);   // low = a, high = b
    return *(unsigned int*)&h;
}
__device__ __forceinline__ void mma_f16(float* c,
                                        unsigned int a0, unsigned int a1,
                                        unsigned int a2, unsigned int a3,
                                        unsigned int b0, unsigned int b1) {
    asm("mma.sync.aligned.m16n8k16.row.col.f32.f16.f16.f32 "
        "{%0,%1,%2,%3}, {%4,%5,%6,%7}, {%8,%9}, {%0,%1,%2,%3};"
        : "+f"(c[0]), "+f"(c[1]), "+f"(c[2]), "+f"(c[3])
        : "r"(a0), "r"(a1), "r"(a2), "r"(a3), "r"(b0), "r"(b1));
}
__device__ __forceinline__ void cp16(unsigned int saddr, const void* gptr) {
    asm volatile("cp.async.cg.shared.global [%0], [%1], 16;" :: "r"(saddr), "l"(gptr));
}
__device__ __forceinline__ void cp4(unsigned int saddr, const void* gptr) {
    asm volatile("cp.async.ca.shared.global [%0], [%1], 4;" :: "r"(saddr), "l"(gptr));
}
__device__ __forceinline__ int sigma3(int g) {   // chunk-swizzle: {0,4,1,5,2,6,3,7}
    return ((g & 1) << 2) | (g >> 1);
}

// ============================================================
// K1: Wh = h @ W ; also emit transposed fp16 copy g_WhT[b][h][d][n]
// ============================================================
__global__ __launch_bounds__(256) void k_gemm(const float* __restrict__ hIn,
                                              const float* __restrict__ W) {
    __shared__ float hs[32 * IND];
    int row0 = blockIdx.x * 32;
    const float4* gp = (const float4*)(hIn + (size_t)row0 * IND);
    float4* sp = (float4*)hs;
    for (int i = threadIdx.x; i < 32 * IND / 4; i += 256) sp[i] = gp[i];
    __syncthreads();

    int c = threadIdx.x;
    float acc[32];
#pragma unroll
    for (int r = 0; r < 32; r++) acc[r] = 0.f;

    for (int k = 0; k < IND; k += 4) {
        float w0 = __ldg(&W[(k + 0) * C + c]);
        float w1 = __ldg(&W[(k + 1) * C + c]);
        float w2 = __ldg(&W[(k + 2) * C + c]);
        float w3 = __ldg(&W[(k + 3) * C + c]);
#pragma unroll
        for (int r = 0; r < 32; r++) {
            float4 hv = *(const float4*)&hs[r * IND + k];
            acc[r] += hv.x * w0 + hv.y * w1 + hv.z * w2 + hv.w * w3;
        }
    }
#pragma unroll
    for (int r = 0; r < 32; r++) g_Wh[(size_t)(row0 + r) * C + c] = acc[r];

    // transposed fp16 copy (rows stay inside one b: 2048 % 32 == 0)
    int b = row0 >> 11;
    int n0 = row0 & (Nn - 1);
    int hh = c >> 6, d = c & 63;
    unsigned int* wt = g_WhT + ((size_t)(((b * Hn + hh) * Dn + d)) * Nn + n0) / 2;
    unsigned int wbuf[16];
#pragma unroll
    for (int m = 0; m < 16; m++) wbuf[m] = packh2(acc[2 * m], acc[2 * m + 1]);
#pragma unroll
    for (int q = 0; q < 4; q++) ((uint4*)wt)[q] = ((uint4*)wbuf)[q];
}

// ============================================================
// K2: src/dst projections (pre-scaled by LOG2E). One warp per (b,n,h).
// ============================================================
__global__ __launch_bounds__(256) void k_srcdst(const float* __restrict__ a) {
    int gw = blockIdx.x * 8 + (threadIdx.x >> 5);
    int lane = threadIdx.x & 31;
    int hh = gw & 3;
    int n  = (gw >> 2) & (Nn - 1);
    int b  = gw >> 13;
    const float2 v  = ((const float2*)(g_Wh + (size_t)(b * Nn + n) * C + hh * Dn))[lane];
    const float2 a1 = ((const float2*)(a + hh * 2 * Dn))[lane];
    const float2 a2 = ((const float2*)(a + hh * 2 * Dn + Dn))[lane];
    float s = v.x * a1.x + v.y * a1.y;
    float d = v.x * a2.x + v.y * a2.y;
#pragma unroll
    for (int o = 16; o > 0; o >>= 1) {
        s += __shfl_xor_sync(0xffffffffu, s, o);
        d += __shfl_xor_sync(0xffffffffu, d, o);
    }
    if (lane == 0) {
        g_src[(b * Hn + hh) * Nn + n] = s * LOG2E;
        g_dst[(b * Hn + hh) * Nn + n] = d * LOG2E;
    }
}

// ============================================================
// K2b: expand adjacency into byte masks (0xFF / 0x00)
// Each thread converts 16 ints -> 16 bytes (one uint4 store).
// ============================================================
__global__ __launch_bounds__(256) void k_maskexp(const int* __restrict__ adj) {
    int idx = blockIdx.x * 256 + threadIdx.x;
    const int4* ap = (const int4*)adj + (size_t)idx * 4;
    unsigned int u[4];
#pragma unroll
    for (int q = 0; q < 4; q++) {
        int4 a = ap[q];
        u[q] = (a.x ? 0xFFu : 0u) | (a.y ? 0xFF00u : 0u)
             | (a.z ? 0xFF0000u : 0u) | (a.w ? 0xFF000000u : 0u);
    }
    ((uint4*)g_maskb)[idx] = *(uint4*)u;
}

// ============================================================
// K3: attention. 256 blocks x 128 thr. CTA tile 128 i x 64 d.
// 4 warps, each m32 x 64d, fp16 mma.m16n8k16.
// Byte-mask tile in smem (chunk ^= r&3, conflict-free LDS.64);
// PRMT expands bytes to half-lane masks; P masked via LOP3-AND.
// Rowsum via B=ones MMAs (fp32 accum, consistent with numerator).
// cp.async double-buffer (Wh + mask + dst), one sync per j-tile.
// ============================================================
__global__ __launch_bounds__(128, 3) void k_attn() {
    __shared__ unsigned int WhT_s[2][64 * 32];       // fp16 pairs: [d][j/2], 8 KB each
    __shared__ float dst_s[2][64];
    __shared__ unsigned char maskb_s[2][128 * 64];   // [i][j] bytes, 8 KB each

    int b  = blockIdx.z, hh = blockIdx.y;
    int i0 = blockIdx.x * 128;
    int t  = threadIdx.x;
    int w  = t >> 5, lane = t & 31;
    int gid = lane >> 2, tig = lane & 3;
    int sg = sigma3(gid);
    const unsigned int BONES = 0x3C003C00u;   // half2(1.0, 1.0)

    int ibase = 32 * w + gid;
    const float* sb = g_src + (b * Hn + hh) * Nn + i0;
    float srcv[4];
#pragma unroll
    for (int rr = 0; rr < 4; rr++) srcv[rr] = sb[ibase + 8 * rr];

    float accA[8][4], accB[8][4];
    float accR[2][4];
#pragma unroll
    for (int dt = 0; dt < 8; dt++)
#pragma unroll
        for (int r = 0; r < 4; r++) { accA[dt][r] = 0.f; accB[dt][r] = 0.f; }
#pragma unroll
    for (int r = 0; r < 4; r++) { accR[0][r] = 0.f; accR[1][r] = 0.f; }

    const unsigned int* WhTg = g_WhT + (size_t)((b * Hn + hh) * Dn) * (Nn / 2);
    const float* db = g_dst + (b * Hn + hh) * Nn;
    const unsigned char* mg0 = g_maskb + (size_t)(i0 + t) * Nn;

    // staging mapping: Wh row d_l = t>>1, chunk-quad c2 = t&1
    int d_l = t >> 1, c2 = t & 1;
    int sgs = sigma3(d_l & 7);
    int tsw = t & 3;                     // mask staging chunk-swizzle for row t

    unsigned int whbase = (unsigned int)__cvta_generic_to_shared(&WhT_s[0][0]);
    unsigned int dstaddr0 = (unsigned int)__cvta_generic_to_shared(&dst_s[0][t & 63]);
    unsigned int mskbase = (unsigned int)__cvta_generic_to_shared(&maskb_s[0][0]);
    const unsigned int WHSTRIDE = 64 * 32 * 4;       // 8 KB
    const unsigned int MSKSTRIDE = 128 * 64;         // 8 KB
    const unsigned int DSTSTRIDE = (unsigned int)((char*)&dst_s[1][0] - (char*)&dst_s[0][0]);

    // mask read offsets: row r=ibase+8rr, logical chunk 2v+(tig>>1), phys ^= r&3
    int moff[4][2];
#pragma unroll
    for (int rr = 0; rr < 4; rr++) {
        int r = ibase + 8 * rr;
#pragma unroll
        for (int v = 0; v < 2; v++) {
            int ch = 2 * v + (tig >> 1);
            moff[rr][v] = r * 64 + ((ch ^ (r & 3)) << 4) + 8 * (tig & 1);
        }
    }

    // ---- stage tile 0 into buffer 0 ----
    {
        const unsigned int* gsrc = WhTg + (size_t)d_l * (Nn / 2);
        unsigned int srow = whbase + d_l * 128;
#pragma unroll
        for (int u = 0; u < 4; u++) {
            int ch = 4 * c2 + u;
            cp16(srow + 16 * (ch ^ sgs), gsrc + 4 * ch);
        }
        unsigned int mrow = mskbase + t * 64;
#pragma unroll
        for (int ch = 0; ch < 4; ch++)
            cp16(mrow + 16 * (ch ^ tsw), mg0 + 16 * ch);
        if (t < 64) cp4(dstaddr0, db + t);
        asm volatile("cp.async.commit_group;");
    }

    for (int jt = 0; jt < 32; jt++) {
        int cur = jt & 1;
        asm volatile("cp.async.wait_group 0;");
        __syncthreads();

        // stage next tile (overlaps with compute below)
        if (jt + 1 < 32) {
            int nxt = cur ^ 1;
            int j0n = (jt + 1) * 64;
            const unsigned int* gsrc = WhTg + (size_t)d_l * (Nn / 2) + j0n / 2;
            unsigned int srow = whbase + nxt * WHSTRIDE + d_l * 128;
#pragma unroll
            for (int u = 0; u < 4; u++) {
                int ch = 4 * c2 + u;
                cp16(srow + 16 * (ch ^ sgs), gsrc + 4 * ch);
            }
            unsigned int mrow = mskbase + nxt * MSKSTRIDE + t * 64;
#pragma unroll
            for (int ch = 0; ch < 4; ch++)
                cp16(mrow + 16 * (ch ^ tsw), mg0 + j0n + 16 * ch);
            if (t < 64) cp4(dstaddr0 + nxt * DSTSTRIDE, db + j0n + t);
            asm volatile("cp.async.commit_group;");
        }

        // ---- phase A: all P for this j-tile, packed + byte-masked ----
        const unsigned char* mtb = &maskb_s[cur][0];
        unsigned int pa[4][4][2];   // [rr][ks][v]
#pragma unroll
        for (int v = 0; v < 2; v++) {
            int jb = 32 * v + 8 * tig;
            float4 dv0 = *(const float4*)&dst_s[cur][jb];
            float4 dv1 = *(const float4*)&dst_s[cur][jb + 4];
            float dj[8] = {dv0.x, dv0.y, dv0.z, dv0.w, dv1.x, dv1.y, dv1.z, dv1.w};
#pragma unroll
            for (int rr = 0; rr < 4; rr++) {
                uint2 mk2 = *(const uint2*)&mtb[moff[rr][v]];
                float sv = srcv[rr];
                float p[8];
#pragma unroll
                for (int c = 0; c < 8; c++) {
                    float e = sv + dj[c];
                    e = fmaxf(e, 0.2f * e);
                    p[c] = ex2(e);
                }
                unsigned int e0 = __byte_perm(mk2.x, 0, 0x1100);
                unsigned int e1 = __byte_perm(mk2.x, 0, 0x3322);
                unsigned int e2 = __byte_perm(mk2.y, 0, 0x1100);
                unsigned int e3 = __byte_perm(mk2.y, 0, 0x3322);
                pa[rr][0][v] = packh2(p[0], p[1]) & e0;
                pa[rr][1][v] = packh2(p[2], p[3]) & e1;
                pa[rr][2][v] = packh2(p[4], p[5]) & e2;
                pa[rr][3][v] = packh2(p[6], p[7]) & e3;
            }
        }

        // ---- rowsum MMAs (B = ones) ----
#pragma unroll
        for (int ks = 0; ks < 4; ks++) {
            mma_f16(accR[0], pa[0][ks][0], pa[1][ks][0], pa[0][ks][1], pa[1][ks][1],
                    BONES, BONES);
            mma_f16(accR[1], pa[2][ks][0], pa[3][ks][0], pa[2][ks][1], pa[3][ks][1],
                    BONES, BONES);
        }

        // ---- phase B: fp16 tensor-core PV ----
        const uint4* tile4 = (const uint4*)&WhT_s[cur][0];
        int c0 = tig ^ sg;
#pragma unroll
        for (int dt = 0; dt < 8; dt++) {
            int rowq = (8 * dt + gid) * 8;
            uint4 v0 = tile4[rowq + c0];
            uint4 v1 = tile4[rowq + (c0 ^ 4)];
            unsigned int bw0[4], bw1[4];
            *(uint4*)bw0 = v0;
            *(uint4*)bw1 = v1;
#pragma unroll
            for (int ks = 0; ks < 4; ks++) {
                mma_f16(accA[dt], pa[0][ks][0], pa[1][ks][0], pa[0][ks][1], pa[1][ks][1],
                        bw0[ks], bw1[ks]);
                mma_f16(accB[dt], pa[2][ks][0], pa[3][ks][0], pa[2][ks][1], pa[3][ks][1],
                        bw0[ks], bw1[ks]);
            }
        }
    }

    // rowsums come straight out of accR (cols 0/2 hold rows rr and rr+1)
    float rsv[4] = {accR[0][0], accR[0][2], accR[1][0], accR[1][2]};
    float inv[4];
#pragma unroll
    for (int rr = 0; rr < 4; rr++) inv[rr] = rsv[rr] > 0.f ? 1.f / rsv[rr] : 0.f;

#pragma unroll
    for (int rr = 0; rr < 4; rr++) {
        float* o = g_hnew + (size_t)(b * Nn + i0 + ibase + 8 * rr) * C + hh * Dn;
        float (*ac)[4] = (rr < 2) ? accA : accB;
        int sel = 2 * (rr & 1);
#pragma unroll
        for (int dt = 0; dt < 8; dt++) {
            int d = 8 * dt + 2 * tig;
            *(float2*)&o[d] = make_float2(ac[dt][sel] * inv[rr], ac[dt][sel + 1] * inv[rr]);
        }
    }
}

// ============================================================
// K4/K5: BatchNorm stats (deterministic two-stage)
// ============================================================
__global__ __launch_bounds__(256) void k_bn_partial() {
    int c = threadIdx.x;
    int r0 = blockIdx.x * 32;
    float s = 0.f, ss = 0.f;
#pragma unroll 8
    for (int r = 0; r < 32; r++) {
        float x = g_hnew[(size_t)(r0 + r) * C + c];
        s += x; ss += x * x;
    }
    g_psum[blockIdx.x * C + c] = s;
    g_psq [blockIdx.x * C + c] = ss;
}

__global__ __launch_bounds__(256) void k_bn_final() {
    int c = threadIdx.x;
    float s = 0.f, ss = 0.f;
#pragma unroll 8
    for (int k = 0; k < 256; k++) {
        s  += g_psum[k * C + c];
        ss += g_psq [k * C + c];
    }
    float m = s * (1.f / (float)ROWS);
    float v = ss * (1.f / (float)ROWS) - m * m;
    v = v > 0.f ? v : 0.f;
    g_mean[c] = m;
    g_rstd[c] = rsqrtf(v + 1e-5f);
}

// ============================================================
// K6: normalize + affine + ELU
// ============================================================
__global__ __launch_bounds__(256) void k_norm(const float* __restrict__ gamma,
                                              const float* __restrict__ beta,
                                              float* __restrict__ out) {
    int idx = blockIdx.x * 256 + threadIdx.x;
    int c = (idx & 63) * 4;
    float4 x = ((const float4*)g_hnew)[idx];
    float4 y;
    y.x = (x.x - g_mean[c + 0]) * g_rstd[c + 0] * gamma[c + 0] + beta[c + 0];
    y.y = (x.y - g_mean[c + 1]) * g_rstd[c + 1] * gamma[c + 1] + beta[c + 1];
    y.z = (x.z - g_mean[c + 2]) * g_rstd[c + 2] * gamma[c + 2] + beta[c + 2];
    y.w = (x.w - g_mean[c + 3]) * g_rstd[c + 3] * gamma[c + 3] + beta[c + 3];
    y.x = y.x > 0.f ? y.x : expm1f(y.x);
    y.y = y.y > 0.f ? y.y : expm1f(y.y);
    y.z = y.z > 0.f ? y.z : expm1f(y.z);
    y.w = y.w > 0.f ? y.w : expm1f(y.w);
    ((float4*)out)[idx] = y;
}

// ============================================================
extern "C" void kernel_launch(void* const* d_in, const int* in_sizes, int n_in,
                              void* d_out, int out_size) {
    const float* h     = (const float*)d_in[0];
    const float* W     = (const float*)d_in[1];
    const float* a     = (const float*)d_in[2];
    const float* gamma = (const float*)d_in[3];
    const float* beta  = (const float*)d_in[4];
    const int*   adj   = (const int*)d_in[5];
    float* out = (float*)d_out;

    k_gemm<<<ROWS / 32, 256>>>(h, W);
    k_srcdst<<<Bn * Nn * Hn / 8, 256>>>(a);
    k_maskexp<<<Nn * Nn / 16 / 256, 256>>>(adj);
    dim3 g(Nn / 128, Hn, Bn);      // 16 x 4 x 4 = 256 blocks, launch #4 for ncu
    k_attn<<<g, 128>>>();
    k_bn_partial<<<256, 256>>>();
    k_bn_final<<<1, 256>>>();
    k_norm<<<ROWS * C / 4 / 256, 256>>>(gamma, beta, out);
}